// round 4
// baseline (speedup 1.0000x reference)
#include <cuda_runtime.h>

#define N_NODES 10000
#define IN_CH   128
#define HID     256
#define OUT_CH  128
#define N_EDGES 640000
#define SCAN_T  1024
#define CHUNK   10          // SCAN_T * CHUNK >= N_NODES

// ---- device scratch (allocation-free: __device__ globals) ----
__device__ int g_is64;                               // 1 if edge_index is int64
__device__ __align__(128) int   g_cnt [N_NODES];     // in-degree (w/o self loop)
__device__ __align__(128) int   g_rs  [N_NODES];     // CSR row start
__device__ __align__(128) int   g_wpos[N_NODES];     // fill cursor
__device__ __align__(128) int   g_csrc[N_EDGES];     // CSR src indices, grouped by dst
__device__ __align__(128) float g_dinv[N_NODES];
__device__ __align__(128) float g_t1  [N_NODES * IN_CH];   // x * dinv[row]
__device__ __align__(128) float g_a1  [N_NODES * IN_CH];   // aggregated layer-1 input
__device__ __align__(128) float g_h   [N_NODES * HID];     // relu(a1@W1 + b1)
__device__ __align__(128) float g_t2  [N_NODES * OUT_CH];  // (h@W2) * dinv[row]

// edge accessors: int32 layout = [src[E] | dst[E]]; int64 layout = same but
// 2 words per element (little-endian: value in the even word).
__device__ __forceinline__ int edge_src(const int* __restrict__ ei, int e, int is64) {
    return is64 ? ei[2 * e] : ei[e];
}
__device__ __forceinline__ int edge_dst(const int* __restrict__ ei, int e, int is64) {
    return is64 ? ei[2 * (N_EDGES + e)] : ei[N_EDGES + e];
}

// ---------------------------------------------------------------------------
// dtype sniffer + cnt init. For int64 values < 2^31, all odd 32-bit words are 0.
__global__ void k_init(const int* __restrict__ ei) {
    int i = blockIdx.x * blockDim.x + threadIdx.x;
    if (i < N_NODES) g_cnt[i] = 0;
    if (i == 0) {
        int nz = 0;
        #pragma unroll
        for (int k = 0; k < 16; k++) nz |= ei[2 * k + 1];
        g_is64 = (nz == 0) ? 1 : 0;
    }
}

__global__ void k_hist(const int* __restrict__ ei) {
    int e = blockIdx.x * blockDim.x + threadIdx.x;
    if (e >= N_EDGES) return;
    int is64 = g_is64;
    atomicAdd(&g_cnt[edge_dst(ei, e, is64)], 1);
}

// single-block exclusive scan of counts -> row starts; also dinv = rsqrt(deg+1)
__global__ void k_scan() {
    __shared__ int partial[SCAN_T];
    int tid = threadIdx.x;
    int start = tid * CHUNK;
    int end = min(start + CHUNK, N_NODES);
    int s = 0;
    for (int i = start; i < end; i++) s += g_cnt[i];
    partial[tid] = s;
    __syncthreads();
    for (int off = 1; off < SCAN_T; off <<= 1) {
        int v = 0;
        if (tid >= off) v = partial[tid - off];
        __syncthreads();
        if (tid >= off) partial[tid] += v;
        __syncthreads();
    }
    int off = (tid == 0) ? 0 : partial[tid - 1];
    for (int i = start; i < end; i++) {
        g_rs[i]   = off;
        g_wpos[i] = off;
        int c = g_cnt[i];
        off += c;
        g_dinv[i] = rsqrtf((float)(c + 1));   // +1 self loop
    }
}

__global__ void k_fill(const int* __restrict__ ei) {
    int e = blockIdx.x * blockDim.x + threadIdx.x;
    if (e >= N_EDGES) return;
    int is64 = g_is64;
    int src = edge_src(ei, e, is64);
    int dst = edge_dst(ei, e, is64);
    int pos = atomicAdd(&g_wpos[dst], 1);
    g_csrc[pos] = src;
}

// t1 = x * dinv[row]   (128 floats/row -> 32 float4/row)
__global__ void k_scale(const float* __restrict__ x) {
    int v = blockIdx.x * blockDim.x + threadIdx.x;
    if (v >= N_NODES * IN_CH / 4) return;
    float dv = g_dinv[v >> 5];
    float4 t = ((const float4*)x)[v];
    t.x *= dv; t.y *= dv; t.z *= dv; t.w *= dv;
    ((float4*)g_t1)[v] = t;
}

// ---------------------------------------------------------------------------
// warp-per-node gather aggregation over 128-float rows (32 x float4)
// mode 0: a1 = dinv * (self + sum_neighbors)                  -> dstbuf
// mode 1: out = relu(dinv * (self + sum_neighbors) + bias)    -> dstbuf
__device__ __forceinline__ void agg_body(const float* __restrict__ t,
                                         float* __restrict__ dstbuf,
                                         const float* __restrict__ bias,
                                         int mode) {
    int gid  = blockIdx.x * blockDim.x + threadIdx.x;
    int node = gid >> 5;
    int lane = gid & 31;
    if (node >= N_NODES) return;

    const float4* t4 = (const float4*)t;
    int deg  = g_cnt[node];
    int base = g_rs[node];
    float dv = g_dinv[node];

    float4 acc = t4[node * 32 + lane];   // self loop (row pre-scaled by dinv[node])

    int i = 0;
    for (; i + 4 <= deg; i += 4) {
        int s0 = g_csrc[base + i + 0];
        int s1 = g_csrc[base + i + 1];
        int s2 = g_csrc[base + i + 2];
        int s3 = g_csrc[base + i + 3];
        float4 v0 = t4[s0 * 32 + lane];
        float4 v1 = t4[s1 * 32 + lane];
        float4 v2 = t4[s2 * 32 + lane];
        float4 v3 = t4[s3 * 32 + lane];
        acc.x += v0.x + v1.x + v2.x + v3.x;
        acc.y += v0.y + v1.y + v2.y + v3.y;
        acc.z += v0.z + v1.z + v2.z + v3.z;
        acc.w += v0.w + v1.w + v2.w + v3.w;
    }
    for (; i < deg; i++) {
        int s = g_csrc[base + i];
        float4 v = t4[s * 32 + lane];
        acc.x += v.x; acc.y += v.y; acc.z += v.z; acc.w += v.w;
    }

    acc.x *= dv; acc.y *= dv; acc.z *= dv; acc.w *= dv;
    if (mode == 1) {
        float4 b = ((const float4*)bias)[lane];
        acc.x = fmaxf(acc.x + b.x, 0.f);
        acc.y = fmaxf(acc.y + b.y, 0.f);
        acc.z = fmaxf(acc.z + b.z, 0.f);
        acc.w = fmaxf(acc.w + b.w, 0.f);
    }
    ((float4*)dstbuf)[node * 32 + lane] = acc;
}

__global__ void k_agg1() { agg_body(g_t1, g_a1, nullptr, 0); }
__global__ void k_agg2(float* __restrict__ out, const float* __restrict__ b2) {
    agg_body(g_t2, out, b2, 1);
}

// ---------------------------------------------------------------------------
// fp32 SGEMM: BM=BN=64, BK=16, 256 thr, 4x4 micro tile
// mode 0: C = relu(AB + bias[col]);  mode 1: C = (AB) * dinv[row]
#define BM 64
#define BN 64
#define BK 16
__device__ __forceinline__ void gemm_body(const float* __restrict__ A,
                                          const float* __restrict__ B,
                                          float* __restrict__ C,
                                          int M, int N, int K,
                                          const float* __restrict__ bias,
                                          int mode) {
    __shared__ float As[BK][BM + 1];
    __shared__ float Bs[BK][BN];
    int tid = threadIdx.x;
    int tx = tid & 15, ty = tid >> 4;
    int row0 = blockIdx.y * BM, col0 = blockIdx.x * BN;
    float acc[4][4] = {};

    for (int k0 = 0; k0 < K; k0 += BK) {
        #pragma unroll
        for (int t = tid; t < BM * BK; t += 256) {
            int m = t >> 4, k = t & 15;
            int gr = row0 + m;
            As[k][m] = (gr < M) ? A[(size_t)gr * K + k0 + k] : 0.f;
        }
        #pragma unroll
        for (int t = tid; t < BK * BN; t += 256) {
            int k = t >> 6, n = t & 63;
            Bs[k][n] = B[(size_t)(k0 + k) * N + col0 + n];
        }
        __syncthreads();
        #pragma unroll
        for (int k = 0; k < BK; k++) {
            float a[4], b[4];
            #pragma unroll
            for (int i = 0; i < 4; i++) a[i] = As[k][ty * 4 + i];
            #pragma unroll
            for (int j = 0; j < 4; j++) b[j] = Bs[k][tx * 4 + j];
            #pragma unroll
            for (int i = 0; i < 4; i++)
                #pragma unroll
                for (int j = 0; j < 4; j++)
                    acc[i][j] += a[i] * b[j];
        }
        __syncthreads();
    }

    #pragma unroll
    for (int i = 0; i < 4; i++) {
        int gr = row0 + ty * 4 + i;
        if (gr >= M) continue;
        float dv = g_dinv[gr];
        #pragma unroll
        for (int j = 0; j < 4; j++) {
            int gc = col0 + tx * 4 + j;
            float v = acc[i][j];
            if (mode == 0) v = fmaxf(v + bias[gc], 0.f);
            else           v = v * dv;
            C[(size_t)gr * N + gc] = v;
        }
    }
}

__global__ void k_gemm1(const float* __restrict__ W1, const float* __restrict__ b1) {
    gemm_body(g_a1, W1, g_h, N_NODES, HID, IN_CH, b1, 0);
}
__global__ void k_gemm2(const float* __restrict__ W2) {
    gemm_body(g_h, W2, g_t2, N_NODES, OUT_CH, HID, nullptr, 1);
}

// ---------------------------------------------------------------------------
extern "C" void kernel_launch(void* const* d_in, const int* in_sizes, int n_in,
                              void* d_out, int out_size) {
    const float* x  = (const float*)d_in[0];
    const int*   ei = (const int*)d_in[1];     // int32 (JAX x64 disabled) or int64 (sniffed)
    const float* W1 = (const float*)d_in[2];
    const float* b1 = (const float*)d_in[3];
    const float* W2 = (const float*)d_in[4];
    const float* b2 = (const float*)d_in[5];
    float* out = (float*)d_out;

    k_init<<<(N_NODES + 255) / 256, 256>>>(ei);
    k_hist<<<(N_EDGES + 255) / 256, 256>>>(ei);
    k_scan<<<1, SCAN_T>>>();
    k_fill<<<(N_EDGES + 255) / 256, 256>>>(ei);
    k_scale<<<(N_NODES * IN_CH / 4 + 255) / 256, 256>>>(x);
    k_agg1<<<(N_NODES * 32 + 255) / 256, 256>>>();
    k_gemm1<<<dim3(HID / BN, (N_NODES + BM - 1) / BM), 256>>>(W1, b1);
    k_gemm2<<<dim3(OUT_CH / BN, (N_NODES + BM - 1) / BM), 256>>>(W2);
    k_agg2<<<(N_NODES * 32 + 255) / 256, 256>>>(out, b2);
}

// round 5
// speedup vs baseline: 1.1945x; 1.1945x over previous
#include <cuda_runtime.h>
#include <mma.h>
using namespace nvcuda;

#define N_NODES 10000
#define M_PAD   10112        // 79 * 128, padded row count for wmma tiles
#define IN_CH   128
#define HID     256
#define OUT_CH  128
#define N_EDGES 640000
#define SCAN_T  1024
#define CHUNK   10           // SCAN_T * CHUNK >= N_NODES

// ---- device scratch (allocation-free: __device__ globals) ----
__device__ int g_is64;                               // 1 if edge_index is int64
__device__ __align__(128) int   g_cnt [N_NODES];     // in-degree (w/o self loop)
__device__ __align__(128) int   g_rs  [N_NODES];     // CSR row start
__device__ __align__(128) int   g_wpos[N_NODES];     // fill cursor
__device__ __align__(128) int   g_csrc[N_EDGES];     // CSR src indices, grouped by dst
__device__ __align__(128) float g_dinv[N_NODES];
__device__ __align__(128) float g_a1  [M_PAD * IN_CH];   // aggregated layer-1 input
__device__ __align__(128) float g_h   [M_PAD * HID];     // a1@W1, then relu(+b1)
__device__ __align__(128) float g_t2  [M_PAD * OUT_CH];  // h@W2 (raw)

// edge accessors: int32 layout = [src[E] | dst[E]]; int64 = 2 words/elt (LE).
__device__ __forceinline__ int edge_src(const int* __restrict__ ei, int e, int is64) {
    return is64 ? ei[2 * e] : ei[e];
}
__device__ __forceinline__ int edge_dst(const int* __restrict__ ei, int e, int is64) {
    return is64 ? ei[2 * (N_EDGES + e)] : ei[N_EDGES + e];
}

// ---------------------------------------------------------------------------
// dtype sniffer + cnt init. For int64 values < 2^31, all odd 32-bit words are 0.
__global__ void k_init(const int* __restrict__ ei) {
    int i = blockIdx.x * blockDim.x + threadIdx.x;
    if (i < N_NODES) g_cnt[i] = 0;
    if (i == 0) {
        int nz = 0;
        #pragma unroll
        for (int k = 0; k < 16; k++) nz |= ei[2 * k + 1];
        g_is64 = (nz == 0) ? 1 : 0;
    }
}

__global__ void k_hist(const int* __restrict__ ei) {
    int e = blockIdx.x * blockDim.x + threadIdx.x;
    if (e >= N_EDGES) return;
    atomicAdd(&g_cnt[edge_dst(ei, e, g_is64)], 1);
}

// single-block exclusive scan of counts -> row starts; also dinv = rsqrt(deg+1)
__global__ void k_scan() {
    __shared__ int partial[SCAN_T];
    int tid = threadIdx.x;
    int start = tid * CHUNK;
    int end = min(start + CHUNK, N_NODES);
    int s = 0;
    for (int i = start; i < end; i++) s += g_cnt[i];
    partial[tid] = s;
    __syncthreads();
    for (int off = 1; off < SCAN_T; off <<= 1) {
        int v = 0;
        if (tid >= off) v = partial[tid - off];
        __syncthreads();
        if (tid >= off) partial[tid] += v;
        __syncthreads();
    }
    int off = (tid == 0) ? 0 : partial[tid - 1];
    for (int i = start; i < end; i++) {
        g_rs[i]   = off;
        g_wpos[i] = off;
        int c = g_cnt[i];
        off += c;
        g_dinv[i] = rsqrtf((float)(c + 1));   // +1 self loop
    }
}

__global__ void k_fill(const int* __restrict__ ei) {
    int e = blockIdx.x * blockDim.x + threadIdx.x;
    if (e >= N_EDGES) return;
    int is64 = g_is64;
    int src = edge_src(ei, e, is64);
    int dst = edge_dst(ei, e, is64);
    int pos = atomicAdd(&g_wpos[dst], 1);
    g_csrc[pos] = src;
}

// ---------------------------------------------------------------------------
// warp-per-node gather aggregation, 128 floats/row, dinv[src] applied on the fly
// mode 0: dst = dinv[n] * (dinv[n]*src_feat[n] + sum_s dinv[s]*src_feat[s])
// mode 1: same, then +bias, relu
__device__ __forceinline__ void agg_body(const float* __restrict__ feat,
                                         float* __restrict__ dstbuf,
                                         const float* __restrict__ bias,
                                         int mode) {
    int gid  = blockIdx.x * blockDim.x + threadIdx.x;
    int node = gid >> 5;
    int lane = gid & 31;
    if (node >= N_NODES) return;

    const float4* f4 = (const float4*)feat;
    int deg  = g_cnt[node];
    int base = g_rs[node];
    float dv = g_dinv[node];

    float4 self = f4[node * 32 + lane];
    float4 acc;
    acc.x = dv * self.x; acc.y = dv * self.y;
    acc.z = dv * self.z; acc.w = dv * self.w;

    int i = 0;
    for (; i + 4 <= deg; i += 4) {
        int s0 = g_csrc[base + i + 0];
        int s1 = g_csrc[base + i + 1];
        int s2 = g_csrc[base + i + 2];
        int s3 = g_csrc[base + i + 3];
        float d0 = g_dinv[s0], d1 = g_dinv[s1], d2 = g_dinv[s2], d3 = g_dinv[s3];
        float4 v0 = f4[s0 * 32 + lane];
        float4 v1 = f4[s1 * 32 + lane];
        float4 v2 = f4[s2 * 32 + lane];
        float4 v3 = f4[s3 * 32 + lane];
        acc.x += d0*v0.x + d1*v1.x + d2*v2.x + d3*v3.x;
        acc.y += d0*v0.y + d1*v1.y + d2*v2.y + d3*v3.y;
        acc.z += d0*v0.z + d1*v1.z + d2*v2.z + d3*v3.z;
        acc.w += d0*v0.w + d1*v1.w + d2*v2.w + d3*v3.w;
    }
    for (; i < deg; i++) {
        int s = g_csrc[base + i];
        float d = g_dinv[s];
        float4 v = f4[s * 32 + lane];
        acc.x += d*v.x; acc.y += d*v.y; acc.z += d*v.z; acc.w += d*v.w;
    }

    acc.x *= dv; acc.y *= dv; acc.z *= dv; acc.w *= dv;
    if (mode == 1) {
        float4 b = ((const float4*)bias)[lane];
        acc.x = fmaxf(acc.x + b.x, 0.f);
        acc.y = fmaxf(acc.y + b.y, 0.f);
        acc.z = fmaxf(acc.z + b.z, 0.f);
        acc.w = fmaxf(acc.w + b.w, 0.f);
    }
    ((float4*)dstbuf)[node * 32 + lane] = acc;
}

__global__ void k_agg1(const float* __restrict__ x) { agg_body(x, g_a1, nullptr, 0); }
__global__ void k_agg2(float* __restrict__ out, const float* __restrict__ b2) {
    agg_body(g_t2, out, b2, 1);
}

// ---------------------------------------------------------------------------
// TF32 wmma GEMM: C = A @ B (raw, no epilogue). A is [M_PAD x K] (padded rows),
// B [K x N], all row-major fp32. Block 128x64x32, 8 warps, warp tile 32x32.
#define BM 128
#define BN 64
#define BK 32
#define APAD 8
#define BPAD 8

__device__ __forceinline__ void gemm_tf32(const float* __restrict__ A,
                                          const float* __restrict__ B,
                                          float* __restrict__ C,
                                          int N, int K) {
    __shared__ float As[BM][BK + APAD];
    __shared__ float Bs[BK][BN + BPAD];
    int tid = threadIdx.x;
    int wid = tid >> 5;
    int warp_m = wid & 3;   // 0..3
    int warp_n = wid >> 2;  // 0..1
    int row0 = blockIdx.y * BM;
    int col0 = blockIdx.x * BN;

    wmma::fragment<wmma::accumulator, 16, 16, 8, float> c[2][2];
    #pragma unroll
    for (int i = 0; i < 2; i++)
        #pragma unroll
        for (int j = 0; j < 2; j++)
            wmma::fill_fragment(c[i][j], 0.f);

    for (int k0 = 0; k0 < K; k0 += BK) {
        #pragma unroll
        for (int t = tid; t < BM * BK / 4; t += 256) {
            int r = t >> 3, c4 = (t & 7) << 2;
            *(float4*)&As[r][c4] =
                *(const float4*)&A[(size_t)(row0 + r) * K + k0 + c4];
        }
        #pragma unroll
        for (int t = tid; t < BK * BN / 4; t += 256) {
            int r = t >> 4, c4 = (t & 15) << 2;
            *(float4*)&Bs[r][c4] =
                *(const float4*)&B[(size_t)(k0 + r) * N + col0 + c4];
        }
        __syncthreads();
        #pragma unroll
        for (int kk = 0; kk < BK; kk += 8) {
            wmma::fragment<wmma::matrix_a, 16, 16, 8, wmma::precision::tf32, wmma::row_major> a[2];
            wmma::fragment<wmma::matrix_b, 16, 16, 8, wmma::precision::tf32, wmma::row_major> b[2];
            #pragma unroll
            for (int i = 0; i < 2; i++) {
                wmma::load_matrix_sync(a[i], &As[warp_m * 32 + i * 16][kk], BK + APAD);
                #pragma unroll
                for (int e = 0; e < a[i].num_elements; e++)
                    a[i].x[e] = wmma::__float_to_tf32(a[i].x[e]);
            }
            #pragma unroll
            for (int j = 0; j < 2; j++) {
                wmma::load_matrix_sync(b[j], &Bs[kk][warp_n * 32 + j * 16], BN + BPAD);
                #pragma unroll
                for (int e = 0; e < b[j].num_elements; e++)
                    b[j].x[e] = wmma::__float_to_tf32(b[j].x[e]);
            }
            #pragma unroll
            for (int i = 0; i < 2; i++)
                #pragma unroll
                for (int j = 0; j < 2; j++)
                    wmma::mma_sync(c[i][j], a[i], b[j], c[i][j]);
        }
        __syncthreads();
    }

    #pragma unroll
    for (int i = 0; i < 2; i++)
        #pragma unroll
        for (int j = 0; j < 2; j++)
            wmma::store_matrix_sync(
                &C[(size_t)(row0 + warp_m * 32 + i * 16) * N + col0 + warp_n * 32 + j * 16],
                c[i][j], N, wmma::mem_row_major);
}

__global__ void k_gemm1(const float* __restrict__ W1) {
    gemm_tf32(g_a1, W1, g_h, HID, IN_CH);
}
__global__ void k_gemm2(const float* __restrict__ W2) {
    gemm_tf32(g_h, W2, g_t2, OUT_CH, HID);
}

// g_h = relu(g_h + b1[col]) over real rows
__global__ void k_bias_relu(const float* __restrict__ b1) {
    int v = blockIdx.x * blockDim.x + threadIdx.x;
    if (v >= N_NODES * HID / 4) return;
    float4 h = ((const float4*)g_h)[v];
    float4 b = ((const float4*)b1)[v & 63];
    h.x = fmaxf(h.x + b.x, 0.f);
    h.y = fmaxf(h.y + b.y, 0.f);
    h.z = fmaxf(h.z + b.z, 0.f);
    h.w = fmaxf(h.w + b.w, 0.f);
    ((float4*)g_h)[v] = h;
}

// ---------------------------------------------------------------------------
extern "C" void kernel_launch(void* const* d_in, const int* in_sizes, int n_in,
                              void* d_out, int out_size) {
    const float* x  = (const float*)d_in[0];
    const int*   ei = (const int*)d_in[1];   // int32 (JAX x64 off) or int64 (sniffed)
    const float* W1 = (const float*)d_in[2];
    const float* b1 = (const float*)d_in[3];
    const float* W2 = (const float*)d_in[4];
    const float* b2 = (const float*)d_in[5];
    float* out = (float*)d_out;

    k_init<<<(N_NODES + 255) / 256, 256>>>(ei);
    k_hist<<<(N_EDGES + 255) / 256, 256>>>(ei);
    k_scan<<<1, SCAN_T>>>();
    k_fill<<<(N_EDGES + 255) / 256, 256>>>(ei);
    k_agg1<<<(N_NODES * 32 + 255) / 256, 256>>>(x);
    k_gemm1<<<dim3(HID / BN, M_PAD / BM), 256>>>(W1);
    k_bias_relu<<<(N_NODES * HID / 4 + 255) / 256, 256>>>(b1);
    k_gemm2<<<dim3(OUT_CH / BN, M_PAD / BM), 256>>>(W2);
    k_agg2<<<(N_NODES * 32 + 255) / 256, 256>>>(out, b2);
}